// round 12
// baseline (speedup 1.0000x reference)
#include <cuda_runtime.h>
#include <cuda_bf16.h>
#include <cstdint>

#define DM 1024
#define NH 16
#define DH 64
#define BB 2
#define TT 2048
#define MT (BB*TT)    // 4096 rows total
#define CH 128        // chunk size
#define NC (TT/CH)    // 16 chunks

// ---- scratch (no allocations allowed) ----
__device__ float g_q[MT*DM];
__device__ float g_k[MT*DM];
__device__ float g_v[MT*DM];
__device__ float g_y[MT*DM];
__device__ float g_part[BB*NH*8*2];
__device__ float g_P2[BB*NH*NC*2*DH*DH];  // split-K partial states (2 halves)
__device__ float g_S[BB*NH*NC*DH*DH];
__device__ __nv_bfloat16 g_ah[MT*DM];     // activation hi
__device__ __nv_bfloat16 g_al[MT*DM];     // activation lo
__device__ __nv_bfloat16 g_wh[4*DM*DM];   // weight hi (q,k,v,o)
__device__ __nv_bfloat16 g_wl[4*DM*DM];   // weight lo

// ============================================================
// helpers
// ============================================================
__device__ __forceinline__ uint32_t smem_u32(const void* p) {
    uint32_t a;
    asm("{ .reg .u64 t; cvta.to.shared.u64 t, %1; cvt.u32.u64 %0, t; }" : "=r"(a) : "l"(p));
    return a;
}

#define CP16(smem_addr, gptr) \
    asm volatile("cp.async.cg.shared.global [%0], [%1], 16;" :: "r"(smem_addr), "l"(gptr))

__device__ __forceinline__ void ldmx4(uint32_t* r, uint32_t addr) {
    asm volatile("ldmatrix.sync.aligned.m8n8.x4.shared.b16 {%0,%1,%2,%3}, [%4];"
        : "=r"(r[0]), "=r"(r[1]), "=r"(r[2]), "=r"(r[3]) : "r"(addr));
}

__device__ __forceinline__ void mma16816(float* d, const uint32_t* a, uint32_t b0, uint32_t b1) {
    asm volatile("mma.sync.aligned.m16n8k16.row.col.f32.bf16.bf16.f32 "
        "{%0,%1,%2,%3}, {%4,%5,%6,%7}, {%8,%9}, {%0,%1,%2,%3};"
        : "+f"(d[0]), "+f"(d[1]), "+f"(d[2]), "+f"(d[3])
        : "r"(a[0]), "r"(a[1]), "r"(a[2]), "r"(a[3]), "r"(b0), "r"(b1));
}

__device__ __forceinline__ void split1(float x, __nv_bfloat16& h, __nv_bfloat16& l) {
    h = __float2bfloat16(x);
    l = __float2bfloat16(x - __bfloat162float(h));
}

// ============================================================
// merged split: one launch covers x (4 quarters) + 4 weights.
// ============================================================
__global__ void split_all(const float* __restrict__ x,
                          const float* __restrict__ Wq, const float* __restrict__ Wk,
                          const float* __restrict__ Wv, const float* __restrict__ Wo,
                          __nv_bfloat16* __restrict__ ah, __nv_bfloat16* __restrict__ al,
                          __nv_bfloat16* __restrict__ wh, __nv_bfloat16* __restrict__ wl)
{
    const int yy = blockIdx.y;
    const size_t i = (size_t)blockIdx.x * blockDim.x + threadIdx.x;
    const size_t e = i * 4;
    const float* src;
    __nv_bfloat16 *hp, *lp;
    if (yy < 4) {
        src = x  + (size_t)yy * (MT*DM/4) + e;
        hp  = ah + (size_t)yy * (MT*DM/4) + e;
        lp  = al + (size_t)yy * (MT*DM/4) + e;
    } else {
        const float* ws[4] = {Wq, Wk, Wv, Wo};
        src = ws[yy-4] + e;
        hp  = wh + (size_t)(yy-4) * DM*DM + e;
        lp  = wl + (size_t)(yy-4) * DM*DM + e;
    }
    float4 xx = *(const float4*)src;
    __nv_bfloat16 h0, h1, h2, h3, l0, l1, l2, l3;
    split1(xx.x, h0, l0); split1(xx.y, h1, l1);
    split1(xx.z, h2, l2); split1(xx.w, h3, l3);
    ((__nv_bfloat162*)hp)[0] = __nv_bfloat162(h0, h1);
    ((__nv_bfloat162*)hp)[1] = __nv_bfloat162(h2, h3);
    ((__nv_bfloat162*)lp)[0] = __nv_bfloat162(l0, l1);
    ((__nv_bfloat162*)lp)[1] = __nv_bfloat162(l2, l3);
}

// ============================================================
// HMMA bf16 GEMM with Ootomo split; batched over blockIdx.z.
// ============================================================
#define GSM_BYTES (2*4*128*40*2)   // 81920

__global__ __launch_bounds__(256, 2)
void gemm_mma(const __nv_bfloat16* __restrict__ Ah, const __nv_bfloat16* __restrict__ Al,
              const __nv_bfloat16* __restrict__ Wh, const __nv_bfloat16* __restrict__ Wl,
              float* __restrict__ C0, float* __restrict__ C1, float* __restrict__ C2,
              int M, int N, int K, int wbase)
{
    extern __shared__ __nv_bfloat16 smh[];
    const uint32_t sbase = smem_u32(smh);
    const int tid = threadIdx.x;
    const int lane = tid & 31;
    const int w = tid >> 5;
    const int wr = w >> 2;
    const int wc = w & 3;
    const int m0 = blockIdx.y * 128;
    const int n0 = blockIdx.x * 128;
    const int z = blockIdx.z;

    float* C = (z == 0) ? C0 : (z == 1) ? C1 : C2;
    const size_t woff = (size_t)(wbase + z) * DM * DM;
    const __nv_bfloat16* Bh = Wh + woff;
    const __nv_bfloat16* Bl = Wl + woff;

    const int lrow = tid >> 2;
    const int lc16 = tid & 3;

    const __nv_bfloat16* gsrc[4] = {Ah, Al, Bh, Bl};

    float acc[4][4][4];
    #pragma unroll
    for (int m = 0; m < 4; m++)
        #pragma unroll
        for (int n = 0; n < 4; n++)
            #pragma unroll
            for (int e = 0; e < 4; e++) acc[m][n][e] = 0.f;

    const int NCH = K >> 5;

    auto load_stage = [&](int s, int k0) {
        uint32_t sb = sbase + (uint32_t)s * 20480u * 2u;
        #pragma unroll
        for (int arr = 0; arr < 4; arr++) {
            const __nv_bfloat16* g = gsrc[arr];
            int base_row = (arr < 2) ? m0 : n0;
            #pragma unroll
            for (int half = 0; half < 2; half++) {
                int row = lrow + half * 64;
                uint32_t so = sb + (uint32_t)(arr * 5120 + row * 40 + lc16 * 8) * 2u;
                const __nv_bfloat16* gp = g + (size_t)(base_row + row) * K + k0 + lc16 * 8;
                CP16(so, gp);
            }
        }
    };

    load_stage(0, 0);
    asm volatile("cp.async.commit_group;" ::: "memory");

    for (int c = 0; c < NCH; ++c) {
        const int s = c & 1;
        if (c + 1 < NCH) {
            load_stage(s ^ 1, (c + 1) << 5);
            asm volatile("cp.async.commit_group;" ::: "memory");
            asm volatile("cp.async.wait_group 1;" ::: "memory");
        } else {
            asm volatile("cp.async.wait_group 0;" ::: "memory");
        }
        __syncthreads();

        const uint32_t sb = sbase + (uint32_t)s * 20480u * 2u;
        const uint32_t sA  = sb;
        const uint32_t sAl = sb + 5120u * 2u;
        const uint32_t sB  = sb + 10240u * 2u;
        const uint32_t sBl = sb + 15360u * 2u;

        #pragma unroll
        for (int kk = 0; kk < 2; ++kk) {
            const int kb = kk * 16;
            uint32_t ah4[4][4], al4[4][4];
            const uint32_t arow = (uint32_t)(wr * 64 + (lane & 15));
            const uint32_t acol = (uint32_t)(kb + (lane >> 4) * 8);
            #pragma unroll
            for (int m = 0; m < 4; m++) {
                uint32_t off = ((arow + m * 16) * 40u + acol) * 2u;
                ldmx4(ah4[m], sA  + off);
                ldmx4(al4[m], sAl + off);
            }
            uint32_t bh4[2][4], bl4[2][4];
            const uint32_t brow = (uint32_t)(wc * 32 + (lane & 7) + ((lane >> 4) << 3));
            const uint32_t bcol = (uint32_t)(kb + ((lane >> 3) & 1) * 8);
            #pragma unroll
            for (int p = 0; p < 2; p++) {
                uint32_t off = ((brow + p * 16) * 40u + bcol) * 2u;
                ldmx4(bh4[p], sB  + off);
                ldmx4(bl4[p], sBl + off);
            }
            #pragma unroll
            for (int m = 0; m < 4; m++) {
                #pragma unroll
                for (int n = 0; n < 4; n++) {
                    uint32_t b0 = bh4[n >> 1][(n & 1) * 2];
                    uint32_t b1 = bh4[n >> 1][(n & 1) * 2 + 1];
                    uint32_t c0 = bl4[n >> 1][(n & 1) * 2];
                    uint32_t c1 = bl4[n >> 1][(n & 1) * 2 + 1];
                    mma16816(acc[m][n], ah4[m], b0, b1);
                    mma16816(acc[m][n], ah4[m], c0, c1);
                    mma16816(acc[m][n], al4[m], b0, b1);
                }
            }
        }
        __syncthreads();
    }

    const int r0 = m0 + wr * 64 + (lane >> 2);
    const int cc = n0 + wc * 32 + (lane & 3) * 2;
    #pragma unroll
    for (int m = 0; m < 4; m++) {
        #pragma unroll
        for (int n = 0; n < 4; n++) {
            float* p0 = C + (size_t)(r0 + m * 16) * N + cc + n * 8;
            float* p1 = C + (size_t)(r0 + m * 16 + 8) * N + cc + n * 8;
            *(float2*)p0 = make_float2(acc[m][n][0], acc[m][n][1]);
            *(float2*)p1 = make_float2(acc[m][n][2], acc[m][n][3]);
        }
    }
}

// ============================================================
// chunk_state split-K: grid (NC, BH, 2); each block does 64 j-rows
// ============================================================
__global__ __launch_bounds__(256)
void chunk_state(const float* __restrict__ kmat, const float* __restrict__ vmat,
                 float* __restrict__ P2)
{
    __shared__ float Ks[64][68];
    __shared__ float Vs[64][68];
    const int ch = blockIdx.x;
    const int bh = blockIdx.y;
    const int z  = blockIdx.z;
    const int b = bh >> 4, h = bh & 15;
    const float lg = log2f(1.f - exp2f(-5.f - (float)h));
    const int tid = threadIdx.x;
    const int j0 = ch * CH + z * 64;

    const float* kbase = kmat + ((size_t)(b*TT + j0))*DM + h*DH;
    const float* vbase = vmat + ((size_t)(b*TT + j0))*DM + h*DH;
    for (int s = tid; s < 64*16; s += 256) {
        int row = s >> 4, c4 = (s & 15) << 2;
        float sc = exp2f(lg * (float)(CH - z*64 - row));
        float4 kk = *(const float4*)(kbase + (size_t)row*DM + c4);
        Ks[row][c4+0] = kk.x*sc; Ks[row][c4+1] = kk.y*sc;
        Ks[row][c4+2] = kk.z*sc; Ks[row][c4+3] = kk.w*sc;
        float4 vv = *(const float4*)(vbase + (size_t)row*DM + c4);
        *(float4*)&Vs[row][c4] = vv;
    }
    __syncthreads();

    const int tr = tid >> 4, tc = tid & 15;
    float acc[4][4];
    #pragma unroll
    for (int i = 0; i < 4; i++)
        #pragma unroll
        for (int j = 0; j < 4; j++) acc[i][j] = 0.f;

    #pragma unroll 4
    for (int j = 0; j < 64; j++) {
        float ar[4], br[4];
        *(float4*)&ar[0] = *(const float4*)&Ks[j][tr*4];
        *(float4*)&br[0] = *(const float4*)&Vs[j][tc*4];
        #pragma unroll
        for (int i = 0; i < 4; i++)
            #pragma unroll
            for (int jj = 0; jj < 4; jj++)
                acc[i][jj] += ar[i] * br[jj];
    }

    float* pbase = P2 + ((size_t)((bh*NC + ch)*2 + z))*DH*DH;
    #pragma unroll
    for (int i = 0; i < 4; i++)
        *(float4*)(pbase + (tr*4 + i)*DH + tc*4) =
            make_float4(acc[i][0], acc[i][1], acc[i][2], acc[i][3]);
}

// ============================================================
// state_scan: parallel over elements.
// ============================================================
__global__ __launch_bounds__(256)
void state_scan(const float* __restrict__ P2, float* __restrict__ S)
{
    const int bh = blockIdx.y;
    const int e = blockIdx.x * 256 + threadIdx.x;   // 0..4095
    const int h = bh & 15;
    const float lg = log2f(1.f - exp2f(-5.f - (float)h));
    const float gC = exp2f(lg * (float)CH);

    float s = 0.f;
    #pragma unroll
    for (int n = 0; n < NC; n++) {
        const size_t sb = ((size_t)(bh*NC + n))*DH*DH;
        const size_t pb = ((size_t)(bh*NC + n))*2*DH*DH;
        S[sb + e] = s * 0.125f;
        float p0 = P2[pb + e];
        float p1 = P2[pb + DH*DH + e];
        s = gC * s + p0 + p1;
    }
}

// ============================================================
// retention via HMMA + Ootomo split.
// Per block (chunk it, bh): Y[128,64] = Qs@Stateᵀ + Σ_jt mask(Qs@Kᵀ)@V
// smem (halves, stride 72): Q hi/lo 128x72, S hi/lo 128x72,
//   B(K or Stᵀ) hi/lo 64x72, C(Vᵀ) hi/lo 64x72  -> 110592 B
// ============================================================
#define RSTR 72
#define RQ_HI 0
#define RQ_LO (128*RSTR)
#define RS_HI (2*128*RSTR)
#define RS_LO (3*128*RSTR)
#define RB_HI (4*128*RSTR)
#define RB_LO (4*128*RSTR + 64*RSTR)
#define RC_HI (4*128*RSTR + 2*64*RSTR)
#define RC_LO (4*128*RSTR + 3*64*RSTR)
#define RETM_BYTES ((4*128*RSTR + 4*64*RSTR) * 2)   // 110592

__device__ __forceinline__ void ret_mma_block(
    uint32_t sb, uint32_t a_hi, uint32_t a_lo, uint32_t b_hi, uint32_t b_lo,
    int wm, int wn, int lane, float (&acc)[2][4][4])
{
    #pragma unroll
    for (int ks = 0; ks < 4; ks++) {
        const int kb = ks * 16;
        uint32_t ahf[2][4], alf[2][4];
        const uint32_t arow = (uint32_t)(wm * 32 + (lane & 15));
        const uint32_t acol = (uint32_t)(kb + (lane >> 4) * 8);
        #pragma unroll
        for (int m = 0; m < 2; m++) {
            uint32_t off = ((arow + m * 16) * (uint32_t)RSTR + acol) * 2u;
            ldmx4(ahf[m], sb + a_hi * 2u + off);
            ldmx4(alf[m], sb + a_lo * 2u + off);
        }
        uint32_t bhf[2][4], blf[2][4];
        const uint32_t brow = (uint32_t)(wn * 32 + (lane & 7) + ((lane >> 4) << 3));
        const uint32_t bcol = (uint32_t)(kb + ((lane >> 3) & 1) * 8);
        #pragma unroll
        for (int p = 0; p < 2; p++) {
            uint32_t off = ((brow + p * 16) * (uint32_t)RSTR + bcol) * 2u;
            ldmx4(bhf[p], sb + b_hi * 2u + off);
            ldmx4(blf[p], sb + b_lo * 2u + off);
        }
        #pragma unroll
        for (int m = 0; m < 2; m++) {
            #pragma unroll
            for (int n = 0; n < 4; n++) {
                uint32_t b0 = bhf[n >> 1][(n & 1) * 2];
                uint32_t b1 = bhf[n >> 1][(n & 1) * 2 + 1];
                uint32_t c0 = blf[n >> 1][(n & 1) * 2];
                uint32_t c1 = blf[n >> 1][(n & 1) * 2 + 1];
                mma16816(acc[m][n], ahf[m], b0, b1);
                mma16816(acc[m][n], ahf[m], c0, c1);
                mma16816(acc[m][n], alf[m], b0, b1);
            }
        }
    }
}

__global__ __launch_bounds__(256, 2)
void retention_mma(const float* __restrict__ q, const float* __restrict__ kmat,
                   const float* __restrict__ vmat, const float* __restrict__ Sg,
                   float* __restrict__ y)
{
    extern __shared__ __nv_bfloat16 smr[];
    const uint32_t sb = smem_u32(smr);
    const int it = blockIdx.x;
    const int bh = blockIdx.y;
    const int b = bh >> 4, h = bh & 15;
    const int i0 = it * CH;
    const float lg = log2f(1.f - exp2f(-5.f - (float)h));
    const int tid = threadIdx.x, lane = tid & 31, w = tid >> 5;
    const int wm = w >> 1, wn = w & 1;

    // ---- load Q (scaled gamma^row, split) row-major ----
    {
        const float* qbase = q + ((size_t)(b*TT + i0))*DM + h*DH;
        for (int s = tid; s < 128*16; s += 256) {
            int row = s >> 4, c4 = (s & 15) << 2;
            float4 a = *(const float4*)(qbase + (size_t)row*DM + c4);
            float sc = exp2f(lg * (float)row);
            __nv_bfloat16 h0,h1,h2,h3,l0,l1,l2,l3;
            split1(a.x*sc,h0,l0); split1(a.y*sc,h1,l1);
            split1(a.z*sc,h2,l2); split1(a.w*sc,h3,l3);
            __nv_bfloat16* qh = smr + RQ_HI + row*RSTR + c4;
            __nv_bfloat16* ql = smr + RQ_LO + row*RSTR + c4;
            ((__nv_bfloat162*)qh)[0] = __nv_bfloat162(h0,h1);
            ((__nv_bfloat162*)qh)[1] = __nv_bfloat162(h2,h3);
            ((__nv_bfloat162*)ql)[0] = __nv_bfloat162(l0,l1);
            ((__nv_bfloat162*)ql)[1] = __nv_bfloat162(l2,l3);
        }
        // load state Stᵀ into B buffer: St[a][c] -> B[c][a]
        const float* sbase = Sg + ((size_t)(bh*NC + it))*DH*DH;
        for (int s = tid; s < 64*16; s += 256) {
            int aa = s >> 4, c4 = (s & 15) << 2;
            float4 v4 = *(const float4*)(sbase + aa*DH + c4);
            __nv_bfloat16 hh, ll;
            split1(v4.x,hh,ll); smr[RB_HI + (c4+0)*RSTR + aa]=hh; smr[RB_LO + (c4+0)*RSTR + aa]=ll;
            split1(v4.y,hh,ll); smr[RB_HI + (c4+1)*RSTR + aa]=hh; smr[RB_LO + (c4+1)*RSTR + aa]=ll;
            split1(v4.z,hh,ll); smr[RB_HI + (c4+2)*RSTR + aa]=hh; smr[RB_LO + (c4+2)*RSTR + aa]=ll;
            split1(v4.w,hh,ll); smr[RB_HI + (c4+3)*RSTR + aa]=hh; smr[RB_LO + (c4+3)*RSTR + aa]=ll;
        }
    }
    __syncthreads();

    float yacc[2][4][4];
    #pragma unroll
    for (int m = 0; m < 2; m++)
        #pragma unroll
        for (int n = 0; n < 4; n++)
            #pragma unroll
            for (int e = 0; e < 4; e++) yacc[m][n][e] = 0.f;

    // ---- inter-chunk: Y += Qs @ Stateᵀ ----
    ret_mma_block(sb, RQ_HI, RQ_LO, RB_HI, RB_LO, wm, wn, lane, yacc);

    // ---- intra-chunk: two 64-j tiles ----
    #pragma unroll
    for (int jt = 0; jt < 2; jt++) {
        const int j0 = i0 + (jt << 6);
        __syncthreads();   // done reading B/C/S from previous phase
        {
            const float* kbase = kmat + ((size_t)(b*TT + j0))*DM + h*DH;
            const float* vbase = vmat + ((size_t)(b*TT + j0))*DM + h*DH;
            for (int s = tid; s < 64*16; s += 256) {
                int row = s >> 4, c4 = (s & 15) << 2;
                // K scaled gamma^{-row}, row-major (B operand [j][c])
                float sc = exp2f(-lg * (float)row);
                float4 kk = *(const float4*)(kbase + (size_t)row*DM + c4);
                __nv_bfloat16 h0,h1,h2,h3,l0,l1,l2,l3;
                split1(kk.x*sc,h0,l0); split1(kk.y*sc,h1,l1);
                split1(kk.z*sc,h2,l2); split1(kk.w*sc,h3,l3);
                __nv_bfloat16* kh = smr + RB_HI + row*RSTR + c4;
                __nv_bfloat16* kl = smr + RB_LO + row*RSTR + c4;
                ((__nv_bfloat162*)kh)[0] = __nv_bfloat162(h0,h1);
                ((__nv_bfloat162*)kh)[1] = __nv_bfloat162(h2,h3);
                ((__nv_bfloat162*)kl)[0] = __nv_bfloat162(l0,l1);
                ((__nv_bfloat162*)kl)[1] = __nv_bfloat162(l2,l3);
                // V transposed into C buffer: V[j][c] -> C[c][j]
                float4 vv = *(const float4*)(vbase + (size_t)row*DM + c4);
                __nv_bfloat16 hh, ll;
                split1(vv.x,hh,ll); smr[RC_HI + (c4+0)*RSTR + row]=hh; smr[RC_LO + (c4+0)*RSTR + row]=ll;
                split1(vv.y,hh,ll); smr[RC_HI + (c4+1)*RSTR + row]=hh; smr[RC_LO + (c4+1)*RSTR + row]=ll;
                split1(vv.z,hh,ll); smr[RC_HI + (c4+2)*RSTR + row]=hh; smr[RC_LO + (c4+2)*RSTR + row]=ll;
                split1(vv.w,hh,ll); smr[RC_HI + (c4+3)*RSTR + row]=hh; smr[RC_LO + (c4+3)*RSTR + row]=ll;
            }
        }
        __syncthreads();

        // S = Qs @ Kᵀ  (128x64 across block; warp computes 32x32)
        float sacc[2][4][4];
        #pragma unroll
        for (int m = 0; m < 2; m++)
            #pragma unroll
            for (int n = 0; n < 4; n++)
                #pragma unroll
                for (int e = 0; e < 4; e++) sacc[m][n][e] = 0.f;
        ret_mma_block(sb, RQ_HI, RQ_LO, RB_HI, RB_LO, wm, wn, lane, sacc);

        // mask + scale + split-store S into smem
        const float base = exp2f(lg * (float)(-(jt << 6))) * 0.125f;
        #pragma unroll
        for (int m = 0; m < 2; m++) {
            #pragma unroll
            for (int n = 0; n < 4; n++) {
                const int ir0 = wm*32 + m*16 + (lane >> 2);
                const int jc0 = wn*32 + n*8 + (lane & 3)*2;
                float v0 = sacc[m][n][0]*base, v1 = sacc[m][n][1]*base;
                float v2 = sacc[m][n][2]*base, v3 = sacc[m][n][3]*base;
                const int jg = jc0 + (jt << 6);
                if (ir0     < jg    ) v0 = 0.f;
                if (ir0     < jg + 1) v1 = 0.f;
                if (ir0 + 8 < jg    ) v2 = 0.f;
                if (ir0 + 8 < jg + 1) v3 = 0.f;
                __nv_bfloat16 h0,h1,h2,h3,l0,l1,l2,l3;
                split1(v0,h0,l0); split1(v1,h1,l1);
                split1(v2,h2,l2); split1(v3,h3,l3);
                *(__nv_bfloat162*)(smr + RS_HI + ir0*RSTR + jc0)     = __nv_bfloat162(h0,h1);
                *(__nv_bfloat162*)(smr + RS_HI + (ir0+8)*RSTR + jc0) = __nv_bfloat162(h2,h3);
                *(__nv_bfloat162*)(smr + RS_LO + ir0*RSTR + jc0)     = __nv_bfloat162(l0,l1);
                *(__nv_bfloat162*)(smr + RS_LO + (ir0+8)*RSTR + jc0) = __nv_bfloat162(l2,l3);
            }
        }
        __syncthreads();

        // Y += S @ V  (A = S smem, B = Vᵀ)
        ret_mma_block(sb, RS_HI, RS_LO, RC_HI, RC_LO, wm, wn, lane, yacc);
    }

    // ---- epilogue ----
    float* ybase = y + ((size_t)(b*TT + i0))*DM + h*DH;
    #pragma unroll
    for (int m = 0; m < 2; m++) {
        #pragma unroll
        for (int n = 0; n < 4; n++) {
            const int ir0 = wm*32 + m*16 + (lane >> 2);
            const int jc0 = wn*32 + n*8 + (lane & 3)*2;
            *(float2*)(ybase + (size_t)ir0*DM + jc0)     = make_float2(yacc[m][n][0], yacc[m][n][1]);
            *(float2*)(ybase + (size_t)(ir0+8)*DM + jc0) = make_float2(yacc[m][n][2], yacc[m][n][3]);
        }
    }
}

// ============================================================
// GroupNorm: phase-1 partial reduce + fused (stats + apply + split)
// ============================================================
__global__ void gn_reduce1(const float* __restrict__ y, float* __restrict__ part)
{
    const int bh = blockIdx.x;
    const int slab = blockIdx.y;
    const int b = bh >> 4, h = bh & 15;
    const float* base = y + (size_t)b*TT*DM + (size_t)slab*(TT/8)*DM + h*DH;
    float s = 0.f, s2 = 0.f;
    for (int sl = threadIdx.x; sl < (TT/8)*16; sl += blockDim.x) {
        int t = sl >> 4, c4 = (sl & 15) << 2;
        float4 vv = *(const float4*)(base + (size_t)t*DM + c4);
        s  += vv.x + vv.y + vv.z + vv.w;
        s2 += vv.x*vv.x + vv.y*vv.y + vv.z*vv.z + vv.w*vv.w;
    }
    #pragma unroll
    for (int o = 16; o > 0; o >>= 1) {
        s  += __shfl_down_sync(0xffffffffu, s,  o);
        s2 += __shfl_down_sync(0xffffffffu, s2, o);
    }
    __shared__ float rs[32], rs2[32];
    const int wid = threadIdx.x >> 5, lid = threadIdx.x & 31;
    if (lid == 0) { rs[wid] = s; rs2[wid] = s2; }
    __syncthreads();
    if (wid == 0) {
        const int nw = blockDim.x >> 5;
        s  = (lid < nw) ? rs[lid]  : 0.f;
        s2 = (lid < nw) ? rs2[lid] : 0.f;
        #pragma unroll
        for (int o = 16; o > 0; o >>= 1) {
            s  += __shfl_down_sync(0xffffffffu, s,  o);
            s2 += __shfl_down_sync(0xffffffffu, s2, o);
        }
        if (lid == 0) {
            part[(bh*8 + slab)*2]   = s;
            part[(bh*8 + slab)*2+1] = s2;
        }
    }
}

__global__ void gn_apply_split(const float* __restrict__ y, const float* __restrict__ part,
                               const float* __restrict__ gw, const float* __restrict__ gb,
                               __nv_bfloat16* __restrict__ hi, __nv_bfloat16* __restrict__ lo)
{
    size_t e = ((size_t)blockIdx.x * blockDim.x + threadIdx.x) * 4;
    int col = (int)(e % DM);
    size_t row = e / DM;
    int b = (int)(row / TT);
    int g = b * 16 + (col >> 6);
    float s = 0.f, s2 = 0.f;
    #pragma unroll
    for (int i = 0; i < 8; i++) {
        s  += part[(g*8 + i)*2];
        s2 += part[(g*8 + i)*2+1];
    }
    const float invN = 1.f / (float)(TT * DH);
    float mean = s * invN;
    float rstd = rsqrtf(s2 * invN - mean * mean + 1e-5f);
    float4 vv = *(const float4*)(y + e);
    float4 w4 = *(const float4*)(gw + col);
    float4 b4 = *(const float4*)(gb + col);
    float o0 = (vv.x - mean) * rstd * w4.x + b4.x;
    float o1 = (vv.y - mean) * rstd * w4.y + b4.y;
    float o2 = (vv.z - mean) * rstd * w4.z + b4.z;
    float o3 = (vv.w - mean) * rstd * w4.w + b4.w;
    __nv_bfloat16 h0, h1, h2, h3, l0, l1, l2, l3;
    split1(o0, h0, l0); split1(o1, h1, l1);
    split1(o2, h2, l2); split1(o3, h3, l3);
    __nv_bfloat162* hp = (__nv_bfloat162*)(hi + e);
    __nv_bfloat162* lp = (__nv_bfloat162*)(lo + e);
    hp[0] = __nv_bfloat162(h0, h1); hp[1] = __nv_bfloat162(h2, h3);
    lp[0] = __nv_bfloat162(l0, l1); lp[1] = __nv_bfloat162(l2, l3);
}

// ============================================================
extern "C" void kernel_launch(void* const* d_in, const int* in_sizes, int n_in,
                              void* d_out, int out_size)
{
    const float* x  = (const float*)d_in[0];
    const float* Wq = (const float*)d_in[1];
    const float* Wk = (const float*)d_in[2];
    const float* Wv = (const float*)d_in[3];
    const float* Wo = (const float*)d_in[4];
    const float* gw = (const float*)d_in[5];
    const float* gb = (const float*)d_in[6];
    float* out = (float*)d_out;

    float *q, *k, *v, *y, *pt, *P2, *S;
    __nv_bfloat16 *ah, *al, *wh, *wl;
    cudaGetSymbolAddress((void**)&q,  g_q);
    cudaGetSymbolAddress((void**)&k,  g_k);
    cudaGetSymbolAddress((void**)&v,  g_v);
    cudaGetSymbolAddress((void**)&y,  g_y);
    cudaGetSymbolAddress((void**)&pt, g_part);
    cudaGetSymbolAddress((void**)&P2, g_P2);
    cudaGetSymbolAddress((void**)&S,  g_S);
    cudaGetSymbolAddress((void**)&ah, g_ah);
    cudaGetSymbolAddress((void**)&al, g_al);
    cudaGetSymbolAddress((void**)&wh, g_wh);
    cudaGetSymbolAddress((void**)&wl, g_wl);

    cudaFuncSetAttribute(gemm_mma, cudaFuncAttributeMaxDynamicSharedMemorySize, GSM_BYTES);
    cudaFuncSetAttribute(retention_mma, cudaFuncAttributeMaxDynamicSharedMemorySize, RETM_BYTES);

    // one merged split launch (x + 4 weights)
    split_all<<<dim3(1024, 8), 256>>>(x, Wq, Wk, Wv, Wo, ah, al, wh, wl);

    // batched QKV GEMM
    dim3 gq(DM/128, MT/128, 3);
    gemm_mma<<<gq, 256, GSM_BYTES>>>(ah, al, wh, wl, q, k, v, MT, DM, DM, 0);

    chunk_state<<<dim3(NC, BB*NH, 2), 256>>>(k, v, P2);
    state_scan<<<dim3(16, BB*NH), 256>>>(P2, S);
    retention_mma<<<dim3(NC, BB*NH), 256, RETM_BYTES>>>(q, k, v, S, y);

    gn_reduce1<<<dim3(BB*NH, 8), 512>>>(y, pt);
    gn_apply_split<<<(MT*DM)/(4*256), 256>>>(y, pt, gw, gb, ah, al);

    // output GEMM (weight index 3)
    dim3 go(DM/128, MT/128, 1);
    gemm_mma<<<go, 256, GSM_BYTES>>>(ah, al, wh, wl, out, out, out, MT, DM, DM, 3);
}